// round 16
// baseline (speedup 1.0000x reference)
#include <cuda_runtime.h>
#include <math.h>

#define H 512
#define W 512
#define HW (512*512)
#define NB 8          // batch
#define NIMG 16       // 8 pred + 8 true
#define NUM_ITER 40
#define BH 16
#define NBANDS (H/BH)   // 32
#define BIGF 3.0e38f
#define PREP_BLOCKS 512

// ---- scratch (device globals; no allocation) ----
// g_skel stores q = 1 - skel  (multiplicative form: q *= (1 - delta))
__device__ float g_imgA[(size_t)NIMG*HW];
__device__ float g_imgB[(size_t)NIMG*HW];
__device__ float g_skel[(size_t)NIMG*HW];
__device__ float g_dicePart[PREP_BLOCKS*3];   // [block][inter,sumT,sumP]
__device__ float g_epPart[NIMG*NBANDS*3];     // [img][band][s,sy,sx]

__device__ __forceinline__ float f3min(float a,float b,float c){return fminf(fminf(a,b),c);}
__device__ __forceinline__ float f3max(float a,float b,float c){return fmaxf(fmaxf(a,b),c);}
__device__ __forceinline__ void pfL1(const float* p) {
    asm volatile("prefetch.global.L1 [%0];" :: "l"(p));
}

// ---------------------------------------------------------------------------
// prep: prob = sigmoid(x1-x0); true->float; dice partials. (vectorized)
// ---------------------------------------------------------------------------
__global__ __launch_bounds__(256) void prep_kernel(const float* __restrict__ net,
                                                   const int* __restrict__ yt) {
    const int b   = blockIdx.x >> 6;          // image 0..7
    const int seg = blockIdx.x & 63;          // segment 0..63
    const int tid = threadIdx.x;
    const float4* x0p = (const float4*)(net + (size_t)b*2*HW);
    const float4* x1p = (const float4*)(net + (size_t)b*2*HW + HW);
    const int4*   ytp = (const int4*)(yt + (size_t)b*HW);
    float4* probp = (float4*)(g_imgA + (size_t)b*HW);
    float4* truep = (float4*)(g_imgA + (size_t)(NB + b)*HW);

    float inter = 0.f, st = 0.f, sp = 0.f;
    #pragma unroll
    for (int j = 0; j < 4; j++) {
        int i = seg*1024 + j*256 + tid;       // float4 index within image
        float4 x0 = x0p[i];
        float4 x1 = x1p[i];
        int4 ti = ytp[i];
        float4 pr;
        pr.x = 1.f / (1.f + __expf(x0.x - x1.x));
        pr.y = 1.f / (1.f + __expf(x0.y - x1.y));
        pr.z = 1.f / (1.f + __expf(x0.z - x1.z));
        pr.w = 1.f / (1.f + __expf(x0.w - x1.w));
        float4 tf = make_float4((float)ti.x, (float)ti.y, (float)ti.z, (float)ti.w);
        probp[i] = pr;
        truep[i] = tf;
        inter += tf.x*pr.x + tf.y*pr.y + tf.z*pr.z + tf.w*pr.w;
        st += tf.x + tf.y + tf.z + tf.w;
        sp += pr.x + pr.y + pr.z + pr.w;
    }
    __shared__ float s[3][256];
    s[0][tid] = inter; s[1][tid] = st; s[2][tid] = sp;
    __syncthreads();
    for (int off = 128; off > 0; off >>= 1) {
        if (tid < off) {
            s[0][tid] += s[0][tid + off];
            s[1][tid] += s[1][tid + off];
            s[2][tid] += s[2][tid + off];
        }
        __syncthreads();
    }
    if (tid == 0) {
        g_dicePart[blockIdx.x*3 + 0] = s[0][0];
        g_dicePart[blockIdx.x*3 + 1] = s[1][0];
        g_dicePart[blockIdx.x*3 + 2] = s[2][0];
    }
}

// ---------------------------------------------------------------------------
// INIT sweep: q = 1 - relu(img - dilate3x3(erode(img))). FULLY UNROLLED.
// ---------------------------------------------------------------------------
__global__ __launch_bounds__(128, 4) void sweep_init_kernel() {
    const int img = blockIdx.y;
    const int R0row = blockIdx.x * BH;
    const int lane = threadIdx.x & 31;
    const int colBase = ((threadIdx.x >> 5) << 7) + (lane << 2);
    const bool isL = (lane == 0), isR = (lane == 31);
    const bool edgeL = (colBase == 0), edgeR = (colBase == W-4);
    const float* __restrict__ in = g_imgA + (size_t)img*HW;
    float* __restrict__ skel = g_skel + (size_t)img*HW;

    const float4 PINF = make_float4(BIGF,BIGF,BIGF,BIGF);
    float4 i0=PINF, i1=PINF, L0=PINF, L1=PINF, Rv0=PINF, Rv1=PINF;
    float4 hp=PINF; float hpL1=BIGF, hpR0=BIGF;
    float4 e1a=make_float4(-BIGF,-BIGF,-BIGF,-BIGF), e1b=e1a;
    float e1aL=-BIGF, e1bL=-BIGF, e1aR=-BIGF, e1bR=-BIGF;

    const int rStart = R0row-2, rEnd = R0row+BH+1;   // BH+4 = 20 rows
    float4 nCur=PINF, nL=PINF, nR=PINF;
    if (rStart >= 0 && rStart < H) {
        const float* p = in + rStart*W + colBase;
        nCur = *(const float4*)p;
        if (isL && !edgeL) nL = *(const float4*)(p - 4);
        if (isR && !edgeR) nR = *(const float4*)(p + 4);
    }

    #pragma unroll
    for (int t = 0; t < BH+4; t++) {
        const int r = rStart + t;
        float4 cur = nCur, Lc = nL, Rc = nR;
        nCur = PINF; nL = PINF; nR = PINF;
        {
            int rn = r + 1;
            if (rn <= rEnd && (unsigned)rn < (unsigned)H) {
                const float* p = in + rn*W + colBase;
                nCur = *(const float4*)p;
                if (isL && !edgeL) nL = *(const float4*)(p - 4);
                if (isR && !edgeR) nR = *(const float4*)(p + 4);
            }
        }
        float xm1 = __shfl_up_sync(0xffffffffu, cur.w, 1); if (isL) xm1 = Lc.w;
        float xp1 = __shfl_down_sync(0xffffffffu, cur.x, 1); if (isR) xp1 = Rc.x;
        float4 hc;
        hc.x = f3min(xm1, cur.x, cur.y);
        hc.y = f3min(cur.x, cur.y, cur.z);
        hc.z = f3min(cur.y, cur.z, cur.w);
        hc.w = f3min(cur.z, cur.w, xp1);
        float hcL1 = f3min(Lc.z, Lc.w, cur.x);
        float hcR0 = f3min(cur.w, Rc.x, Rc.y);

        float4 e1n;
        e1n.x = fminf(f3min(i0.x,i1.x,cur.x), hp.x);
        e1n.y = fminf(f3min(i0.y,i1.y,cur.y), hp.y);
        e1n.z = fminf(f3min(i0.z,i1.z,cur.z), hp.z);
        e1n.w = fminf(f3min(i0.w,i1.w,cur.w), hp.w);
        float e1nL = fminf(f3min(L0.w,L1.w,Lc.w), hpL1);
        float e1nR = fminf(f3min(Rv0.x,Rv1.x,Rc.x), hpR0);
        {
            int k = r-1;
            if (k < 0 || k >= H) {
                e1n = make_float4(-BIGF,-BIGF,-BIGF,-BIGF);
                e1nL = e1nR = -BIGF;
            }
        }
        if (edgeL) e1nL = -BIGF;
        if (edgeR) e1nR = -BIGF;

        if (t >= 4) {   // r >= R0row+2
            float4 mv;
            mv.x = f3max(e1a.x, e1b.x, e1n.x);
            mv.y = f3max(e1a.y, e1b.y, e1n.y);
            mv.z = f3max(e1a.z, e1b.z, e1n.z);
            mv.w = f3max(e1a.w, e1b.w, e1n.w);
            float mvL = f3max(e1aL, e1bL, e1nL);
            float mvR = f3max(e1aR, e1bR, e1nR);
            float mm1 = __shfl_up_sync(0xffffffffu, mv.w, 1); if (isL) mm1 = mvL;
            float mp1 = __shfl_down_sync(0xffffffffu, mv.x, 1); if (isR) mp1 = mvR;
            float4 open;
            open.x = f3max(mm1, mv.x, mv.y);
            open.y = f3max(mv.x, mv.y, mv.z);
            open.z = f3max(mv.y, mv.z, mv.w);
            open.w = f3max(mv.z, mv.w, mp1);
            int k2 = r-2;
            float4 s;
            s.x = 1.f - fmaxf(i0.x - open.x, 0.f);
            s.y = 1.f - fmaxf(i0.y - open.y, 0.f);
            s.z = 1.f - fmaxf(i0.z - open.z, 0.f);
            s.w = 1.f - fmaxf(i0.w - open.w, 0.f);
            *(float4*)(skel + k2*W + colBase) = s;
        }
        i0=i1; i1=cur; L0=L1; L1=Lc; Rv0=Rv1; Rv1=Rc;
        hp=hc; hpL1=hcL1; hpR0=hcR0;
        e1a=e1b; e1b=e1n; e1aL=e1bL; e1bL=e1nL; e1aR=e1bR; e1bR=e1nR;
    }
}

// ---------------------------------------------------------------------------
// STEP body (iterations 0..38), FULLY UNROLLED + register-free L1 prefetch
// two rows ahead (img + skel lines -> next row's register loads hit L1).
// ---------------------------------------------------------------------------
template<bool BOUNDARY>
__device__ __forceinline__ void step_body(
    const float* __restrict__ in, float* __restrict__ outImg,
    float* __restrict__ skel, int R0row, int colBase,
    bool isL, bool isR, bool edgeL, bool edgeR)
{
    const float4 PINF = make_float4(BIGF,BIGF,BIGF,BIGF);
    const float4 NINF = make_float4(-BIGF,-BIGF,-BIGF,-BIGF);

    float4 i0=PINF, i1=PINF, L0=PINF, L1=PINF, Rv0=PINF, Rv1=PINF;
    float4 hp=PINF; float hpL0=BIGF, hpL1=BIGF, hpR0=BIGF, hpR1=BIGF;
    float4 e1a=PINF, e1b=PINF; float e1aL=BIGF, e1bL=BIGF, e1aR=BIGF, e1bR=BIGF;
    float4 h1p=PINF; float h1pL=BIGF, h1pR=BIGF;
    float4 e2a=NINF, e2b=NINF; float e2aL=-BIGF, e2bL=-BIGF, e2aR=-BIGF, e2bR=-BIGF;

    const int rStart = R0row-3, rEnd = R0row+BH+2;   // BH+6 = 22 rows
    float4 nCur=PINF, nL=PINF, nR=PINF, nSk=make_float4(0,0,0,0);
    if (!BOUNDARY || (rStart >= 0 && rStart < H)) {
        const float* p = in + rStart*W + colBase;
        nCur = *(const float4*)p;
        if (isL && !edgeL) nL = *(const float4*)(p - 4);
        if (isR && !edgeR) nR = *(const float4*)(p + 4);
    }

    #pragma unroll
    for (int t = 0; t < BH+6; t++) {
        const int r = rStart + t;
        float4 cur = nCur, Lc = nL, Rc = nR, skv = nSk;
        {
            int rn = r + 1;
            if (BOUNDARY) {
                nCur = PINF; nL = PINF; nR = PINF;
                if (rn <= rEnd && (unsigned)rn < (unsigned)H) {
                    const float* p = in + rn*W + colBase;
                    nCur = *(const float4*)p;
                    if (isL && !edgeL) nL = *(const float4*)(p - 4);
                    if (isR && !edgeR) nR = *(const float4*)(p + 4);
                }
                if (rn >= R0row+3 && rn <= rEnd)
                    nSk = *(const float4*)(skel + (rn-3)*W + colBase);
                // register-free L1 prefetch two rows ahead
                int rp = r + 2;
                if (t+2 <= BH+5) {
                    if ((unsigned)rp < (unsigned)H) pfL1(in + rp*W + colBase);
                    int qr = rp - 3;
                    if (t+2 >= 6 && (unsigned)qr < (unsigned)H)
                        pfL1(skel + qr*W + colBase);
                }
            } else {
                const float* p = in + rn*W + colBase;
                nCur = *(const float4*)p;
                nL = PINF; nR = PINF;
                if (isL && !edgeL) nL = *(const float4*)(p - 4);
                if (isR && !edgeR) nR = *(const float4*)(p + 4);
                nSk = *(const float4*)(skel + (rn-3)*W + colBase);
                // register-free L1 prefetch two rows ahead (rows provably valid)
                if (t+2 <= BH+5) {
                    int rp = r + 2;
                    pfL1(in + rp*W + colBase);
                    pfL1(skel + (rp-3)*W + colBase);
                }
            }
        }
        float xm1 = __shfl_up_sync(0xffffffffu, cur.w, 1); if (isL) xm1 = Lc.w;
        float xp1 = __shfl_down_sync(0xffffffffu, cur.x, 1); if (isR) xp1 = Rc.x;
        float4 hc;
        hc.x = f3min(xm1, cur.x, cur.y);
        hc.y = f3min(cur.x, cur.y, cur.z);
        hc.z = f3min(cur.y, cur.z, cur.w);
        hc.w = f3min(cur.z, cur.w, xp1);
        float hcL0 = f3min(Lc.y, Lc.z, Lc.w);
        float hcL1 = f3min(Lc.z, Lc.w, cur.x);
        float hcR0 = f3min(cur.w, Rc.x, Rc.y);
        float hcR1 = f3min(Rc.x, Rc.y, Rc.z);

        float4 e1n;
        e1n.x = fminf(f3min(i0.x,i1.x,cur.x), hp.x);
        e1n.y = fminf(f3min(i0.y,i1.y,cur.y), hp.y);
        e1n.z = fminf(f3min(i0.z,i1.z,cur.z), hp.z);
        e1n.w = fminf(f3min(i0.w,i1.w,cur.w), hp.w);
        float e1nL0 = fminf(f3min(L0.z,L1.z,Lc.z), hpL0);
        float e1nL1 = fminf(f3min(L0.w,L1.w,Lc.w), hpL1);
        float e1nR0 = fminf(f3min(Rv0.x,Rv1.x,Rc.x), hpR0);
        float e1nR1 = fminf(f3min(Rv0.y,Rv1.y,Rc.y), hpR1);
        if (BOUNDARY) {
            int k = r-1;
            if (k < 0 || k >= H) { e1n = PINF; e1nL0=e1nL1=e1nR0=e1nR1=BIGF; }
        }
        float em1 = __shfl_up_sync(0xffffffffu, e1n.w, 1); if (isL) em1 = e1nL1;
        float ep1 = __shfl_down_sync(0xffffffffu, e1n.x, 1); if (isR) ep1 = e1nR0;
        float4 h1c;
        h1c.x = f3min(em1, e1n.x, e1n.y);
        h1c.y = f3min(e1n.x, e1n.y, e1n.z);
        h1c.z = f3min(e1n.y, e1n.z, e1n.w);
        h1c.w = f3min(e1n.z, e1n.w, ep1);
        float h1cL = f3min(e1nL0, e1nL1, e1n.x);
        float h1cR = f3min(e1n.w, e1nR0, e1nR1);

        float4 e2n;
        e2n.x = fminf(f3min(e1a.x,e1b.x,e1n.x), h1p.x);
        e2n.y = fminf(f3min(e1a.y,e1b.y,e1n.y), h1p.y);
        e2n.z = fminf(f3min(e1a.z,e1b.z,e1n.z), h1p.z);
        e2n.w = fminf(f3min(e1a.w,e1b.w,e1n.w), h1p.w);
        float e2nL = fminf(f3min(e1aL,e1bL,e1nL1), h1pL);
        float e2nR = fminf(f3min(e1aR,e1bR,e1nR0), h1pR);
        if (BOUNDARY) {
            int j = r-2;
            if (j < 0 || j >= H) { e2n = NINF; e2nL = e2nR = -BIGF; }
        }
        if (edgeL) e2nL = -BIGF;
        if (edgeR) e2nR = -BIGF;

        if (t >= 6) {
            float4 mv;
            mv.x = f3max(e2a.x, e2b.x, e2n.x);
            mv.y = f3max(e2a.y, e2b.y, e2n.y);
            mv.z = f3max(e2a.z, e2b.z, e2n.z);
            mv.w = f3max(e2a.w, e2b.w, e2n.w);
            float mvL = f3max(e2aL, e2bL, e2nL);
            float mvR = f3max(e2aR, e2bR, e2nR);
            float mm1 = __shfl_up_sync(0xffffffffu, mv.w, 1); if (isL) mm1 = mvL;
            float mp1 = __shfl_down_sync(0xffffffffu, mv.x, 1); if (isR) mp1 = mvR;
            float4 open;
            open.x = f3max(mm1, mv.x, mv.y);
            open.y = f3max(mv.x, mv.y, mv.z);
            open.z = f3max(mv.y, mv.z, mv.w);
            open.w = f3max(mv.z, mv.w, mp1);
            int k2 = r-3;
            float4 ec = e1a;
            float4 q = skv;
            float d0 = fmaxf(ec.x - open.x, 0.f); q.x -= q.x*d0;
            float d1 = fmaxf(ec.y - open.y, 0.f); q.y -= q.y*d1;
            float d2 = fmaxf(ec.z - open.z, 0.f); q.z -= q.z*d2;
            float d3 = fmaxf(ec.w - open.w, 0.f); q.w -= q.w*d3;
            *(float4*)(skel + k2*W + colBase) = q;
            *(float4*)(outImg + k2*W + colBase) = ec;
        }
        i0=i1; i1=cur; L0=L1; L1=Lc; Rv0=Rv1; Rv1=Rc;
        hp=hc; hpL0=hcL0; hpL1=hcL1; hpR0=hcR0; hpR1=hcR1;
        e1a=e1b; e1b=e1n; e1aL=e1bL; e1bL=e1nL1; e1aR=e1bR; e1bR=e1nR0;
        h1p=h1c; h1pL=h1cL; h1pR=h1cR;
        e2a=e2b; e2b=e2n; e2aL=e2bL; e2bL=e2nL; e2aR=e2bR; e2bR=e2nR;
    }
}

__global__ __launch_bounds__(128, 4) void sweep_step_kernel(int bufsel) {
    const int img = blockIdx.y;
    const int band = blockIdx.x;
    const int R0row = band * BH;
    const int lane = threadIdx.x & 31;
    const int colBase = ((threadIdx.x >> 5) << 7) + (lane << 2);
    const bool isL = (lane == 0), isR = (lane == 31);
    const bool edgeL = (colBase == 0), edgeR = (colBase == W-4);
    const float* __restrict__ in     = (bufsel ? g_imgB : g_imgA) + (size_t)img*HW;
    float*       __restrict__ outImg = (bufsel ? g_imgA : g_imgB) + (size_t)img*HW;
    float*       __restrict__ skel   = g_skel + (size_t)img*HW;

    if (band == 0 || band == NBANDS-1)
        step_body<true >(in, outImg, skel, R0row, colBase, isL, isR, edgeL, edgeR);
    else
        step_body<false>(in, outImg, skel, R0row, colBase, isL, isR, edgeL, edgeR);
}

// ---------------------------------------------------------------------------
// FINAL fused kernel: last morphology iteration + endpoint conv + partials.
// (unchanged from R15 winner)
// ---------------------------------------------------------------------------
#define SROWS 18
#define SPITCH 516
template<bool BOUNDARY>
__device__ __forceinline__ void final_body(
    const float* __restrict__ in, const float* __restrict__ skel,
    int R0row, int colBase,
    bool isL, bool isR, bool edgeL, bool edgeR,
    float (*sk_s)[SPITCH])
{
    const float4 PINF = make_float4(BIGF,BIGF,BIGF,BIGF);
    const float4 NINF = make_float4(-BIGF,-BIGF,-BIGF,-BIGF);

    float4 i0=PINF, i1=PINF, L0=PINF, L1=PINF, Rv0=PINF, Rv1=PINF;
    float4 hp=PINF; float hpL0=BIGF, hpL1=BIGF, hpR0=BIGF, hpR1=BIGF;
    float4 e1a=PINF, e1b=PINF; float e1aL=BIGF, e1bL=BIGF, e1aR=BIGF, e1bR=BIGF;
    float4 h1p=PINF; float h1pL=BIGF, h1pR=BIGF;
    float4 e2a=NINF, e2b=NINF; float e2aL=-BIGF, e2bL=-BIGF, e2aR=-BIGF, e2bR=-BIGF;

    const int rStart = R0row-4;               // 24 rows: t = 0..BH+7
    float4 nCur=PINF, nL=PINF, nR=PINF, nSk=make_float4(0,0,0,0);
    if (!BOUNDARY || ((unsigned)rStart < (unsigned)H)) {
        const float* p = in + rStart*W + colBase;
        nCur = *(const float4*)p;
        if (isL && !edgeL) nL = *(const float4*)(p - 4);
        if (isR && !edgeR) nR = *(const float4*)(p + 4);
    }

    #pragma unroll
    for (int t = 0; t < BH+8; t++) {
        const int r = rStart + t;
        float4 cur = nCur, Lc = nL, Rc = nR, skv = nSk;
        {
            int rn = r + 1;   // prefetch img row rn and q row rn-3
            if (BOUNDARY) {
                nCur = PINF; nL = PINF; nR = PINF;
                if ((unsigned)rn < (unsigned)H && t+1 <= BH+7) {
                    const float* p = in + rn*W + colBase;
                    nCur = *(const float4*)p;
                    if (isL && !edgeL) nL = *(const float4*)(p - 4);
                    if (isR && !edgeR) nR = *(const float4*)(p + 4);
                }
                nSk = make_float4(0,0,0,0);
                if (t+1 >= 6 && t+1 <= BH+7 && (unsigned)(rn-3) < (unsigned)H)
                    nSk = *(const float4*)(skel + (rn-3)*W + colBase);
            } else {
                if (t+1 <= BH+7) {
                    const float* p = in + rn*W + colBase;
                    nCur = *(const float4*)p;
                    nL = PINF; nR = PINF;
                    if (isL && !edgeL) nL = *(const float4*)(p - 4);
                    if (isR && !edgeR) nR = *(const float4*)(p + 4);
                }
                if (t+1 >= 6 && t+1 <= BH+7)
                    nSk = *(const float4*)(skel + (rn-3)*W + colBase);
            }
        }
        float xm1 = __shfl_up_sync(0xffffffffu, cur.w, 1); if (isL) xm1 = Lc.w;
        float xp1 = __shfl_down_sync(0xffffffffu, cur.x, 1); if (isR) xp1 = Rc.x;
        float4 hc;
        hc.x = f3min(xm1, cur.x, cur.y);
        hc.y = f3min(cur.x, cur.y, cur.z);
        hc.z = f3min(cur.y, cur.z, cur.w);
        hc.w = f3min(cur.z, cur.w, xp1);
        float hcL0 = f3min(Lc.y, Lc.z, Lc.w);
        float hcL1 = f3min(Lc.z, Lc.w, cur.x);
        float hcR0 = f3min(cur.w, Rc.x, Rc.y);
        float hcR1 = f3min(Rc.x, Rc.y, Rc.z);

        float4 e1n;
        e1n.x = fminf(f3min(i0.x,i1.x,cur.x), hp.x);
        e1n.y = fminf(f3min(i0.y,i1.y,cur.y), hp.y);
        e1n.z = fminf(f3min(i0.z,i1.z,cur.z), hp.z);
        e1n.w = fminf(f3min(i0.w,i1.w,cur.w), hp.w);
        float e1nL0 = fminf(f3min(L0.z,L1.z,Lc.z), hpL0);
        float e1nL1 = fminf(f3min(L0.w,L1.w,Lc.w), hpL1);
        float e1nR0 = fminf(f3min(Rv0.x,Rv1.x,Rc.x), hpR0);
        float e1nR1 = fminf(f3min(Rv0.y,Rv1.y,Rc.y), hpR1);
        if (BOUNDARY) {
            int k = r-1;
            if (k < 0 || k >= H) { e1n = PINF; e1nL0=e1nL1=e1nR0=e1nR1=BIGF; }
        }
        float em1 = __shfl_up_sync(0xffffffffu, e1n.w, 1); if (isL) em1 = e1nL1;
        float ep1 = __shfl_down_sync(0xffffffffu, e1n.x, 1); if (isR) ep1 = e1nR0;
        float4 h1c;
        h1c.x = f3min(em1, e1n.x, e1n.y);
        h1c.y = f3min(e1n.x, e1n.y, e1n.z);
        h1c.z = f3min(e1n.y, e1n.z, e1n.w);
        h1c.w = f3min(e1n.z, e1n.w, ep1);
        float h1cL = f3min(e1nL0, e1nL1, e1n.x);
        float h1cR = f3min(e1n.w, e1nR0, e1nR1);

        float4 e2n;
        e2n.x = fminf(f3min(e1a.x,e1b.x,e1n.x), h1p.x);
        e2n.y = fminf(f3min(e1a.y,e1b.y,e1n.y), h1p.y);
        e2n.z = fminf(f3min(e1a.z,e1b.z,e1n.z), h1p.z);
        e2n.w = fminf(f3min(e1a.w,e1b.w,e1n.w), h1p.w);
        float e2nL = fminf(f3min(e1aL,e1bL,e1nL1), h1pL);
        float e2nR = fminf(f3min(e1aR,e1bR,e1nR0), h1pR);
        if (BOUNDARY) {
            int j = r-2;
            if (j < 0 || j >= H) { e2n = NINF; e2nL = e2nR = -BIGF; }
        }
        if (edgeL) e2nL = -BIGF;
        if (edgeR) e2nR = -BIGF;

        if (t >= 6) {   // out row k2 = r-3 in [R0row-1, R0row+BH]; smem row t-6
            const int k2 = r-3;
            const int srow = t-6;
            float4 sv = make_float4(0,0,0,0);   // zero-pad for invalid rows
            if (!BOUNDARY || ((unsigned)k2 < (unsigned)H)) {
                float4 mv;
                mv.x = f3max(e2a.x, e2b.x, e2n.x);
                mv.y = f3max(e2a.y, e2b.y, e2n.y);
                mv.z = f3max(e2a.z, e2b.z, e2n.z);
                mv.w = f3max(e2a.w, e2b.w, e2n.w);
                float mvL = f3max(e2aL, e2bL, e2nL);
                float mvR = f3max(e2aR, e2bR, e2nR);
                float mm1 = __shfl_up_sync(0xffffffffu, mv.w, 1); if (isL) mm1 = mvL;
                float mp1 = __shfl_down_sync(0xffffffffu, mv.x, 1); if (isR) mp1 = mvR;
                float4 open;
                open.x = f3max(mm1, mv.x, mv.y);
                open.y = f3max(mv.x, mv.y, mv.z);
                open.z = f3max(mv.y, mv.z, mv.w);
                open.w = f3max(mv.z, mv.w, mp1);
                float4 ec = e1a;
                float4 q = skv;
                float d0 = fmaxf(ec.x - open.x, 0.f); q.x -= q.x*d0;
                float d1 = fmaxf(ec.y - open.y, 0.f); q.y -= q.y*d1;
                float d2 = fmaxf(ec.z - open.z, 0.f); q.z -= q.z*d2;
                float d3 = fmaxf(ec.w - open.w, 0.f); q.w -= q.w*d3;
                sv = make_float4(1.f-q.x, 1.f-q.y, 1.f-q.z, 1.f-q.w);
            } else {
                // keep warp-uniform shfl execution even when row invalid
                float4 mv;
                mv.x = f3max(e2a.x, e2b.x, e2n.x);
                mv.w = f3max(e2a.w, e2b.w, e2n.w);
                (void)__shfl_up_sync(0xffffffffu, mv.w, 1);
                (void)__shfl_down_sync(0xffffffffu, mv.x, 1);
            }
            *(float4*)&sk_s[srow][colBase] = sv;
        }
        i0=i1; i1=cur; L0=L1; L1=Lc; Rv0=Rv1; Rv1=Rc;
        hp=hc; hpL0=hcL0; hpL1=hcL1; hpR0=hcR0; hpR1=hcR1;
        e1a=e1b; e1b=e1n; e1aL=e1bL; e1bL=e1nL1; e1aR=e1bR; e1bR=e1nR0;
        h1p=h1c; h1pL=h1cL; h1pR=h1cR;
        e2a=e2b; e2b=e2n; e2aL=e2bL; e2bL=e2nL; e2aR=e2bR; e2bR=e2nR;
    }
}

__global__ __launch_bounds__(128, 4) void final_step_kernel(int bufsel) {
    const int img = blockIdx.y;
    const int band = blockIdx.x;
    const int R0row = band * BH;
    const int lane = threadIdx.x & 31;
    const int colBase = ((threadIdx.x >> 5) << 7) + (lane << 2);
    const bool isL = (lane == 0), isR = (lane == 31);
    const bool edgeL = (colBase == 0), edgeR = (colBase == W-4);
    const float* __restrict__ in   = (bufsel ? g_imgB : g_imgA) + (size_t)img*HW;
    const float* __restrict__ skel = g_skel + (size_t)img*HW;

    __shared__ float sk_s[SROWS][SPITCH];

    if (band == 0 || band == NBANDS-1)
        final_body<true >(in, skel, R0row, colBase, isL, isR, edgeL, edgeR, sk_s);
    else
        final_body<false>(in, skel, R0row, colBase, isL, isR, edgeL, edgeR, sk_s);

    __syncthreads();

    float r0c[6], r1c[6], r2c[6];
    #pragma unroll
    for (int j = 0; j < 6; j++) { r0c[j] = 0.f; r1c[j] = 0.f; }
    {
        #pragma unroll
        for (int s = 0; s < 2; s++) {
            float* dst = s ? r1c : r0c;
            const float* row = sk_s[s];
            dst[0] = edgeL ? 0.f : row[colBase-1];
            float4 v = *(const float4*)&row[colBase];
            dst[1]=v.x; dst[2]=v.y; dst[3]=v.z; dst[4]=v.w;
            dst[5] = edgeR ? 0.f : row[colBase+4];
        }
    }
    float s0 = 0.f, sy = 0.f, sx = 0.f;
    #pragma unroll
    for (int kk = 0; kk < BH; kk++) {
        const float* row = sk_s[kk+2];
        r2c[0] = edgeL ? 0.f : row[colBase-1];
        float4 v = *(const float4*)&row[colBase];
        r2c[1]=v.x; r2c[2]=v.y; r2c[3]=v.z; r2c[4]=v.w;
        r2c[5] = edgeR ? 0.f : row[colBase+4];

        float vs0 = r0c[0]+r1c[0]+r2c[0];
        float vs1 = r0c[1]+r1c[1]+r2c[1];
        float vs2 = r0c[2]+r1c[2]+r2c[2];
        float vs3 = r0c[3]+r1c[3]+r2c[3];
        float vs4 = r0c[4]+r1c[4]+r2c[4];
        float vs5 = r0c[5]+r1c[5]+r2c[5];
        float c0 = r1c[1], c1 = r1c[2], c2 = r1c[3], c3 = r1c[4];
        float ns0 = vs0+vs1+vs2 + 9.f*c0;
        float ns1 = vs1+vs2+vs3 + 9.f*c1;
        float ns2 = vs2+vs3+vs4 + 9.f*c2;
        float ns3 = vs3+vs4+vs5 + 9.f*c3;
        float d0 = ns0-11.f, d1 = ns1-11.f, d2 = ns2-11.f, d3 = ns3-11.f;
        float e0 = __expf(-d0*d0)*c0;
        float e1 = __expf(-d1*d1)*c1;
        float e2 = __expf(-d2*d2)*c2;
        float e3 = __expf(-d3*d3)*c3;
        float es = e0+e1+e2+e3;
        s0 += es;
        sy += es * (float)(R0row + kk);
        sx += e0*(float)colBase + e1*(float)(colBase+1)
            + e2*(float)(colBase+2) + e3*(float)(colBase+3);
        #pragma unroll
        for (int j = 0; j < 6; j++) { r0c[j] = r1c[j]; r1c[j] = r2c[j]; }
    }

    __syncthreads();
    __shared__ float s[3][128];
    s[0][threadIdx.x] = s0; s[1][threadIdx.x] = sy; s[2][threadIdx.x] = sx;
    __syncthreads();
    for (int off = 64; off > 0; off >>= 1) {
        if (threadIdx.x < off) {
            s[0][threadIdx.x] += s[0][threadIdx.x + off];
            s[1][threadIdx.x] += s[1][threadIdx.x + off];
            s[2][threadIdx.x] += s[2][threadIdx.x + off];
        }
        __syncthreads();
    }
    if (threadIdx.x == 0) {
        int o = (img*NBANDS + band)*3;
        g_epPart[o + 0] = s[0][0];
        g_epPart[o + 1] = s[1][0];
        g_epPart[o + 2] = s[2][0];
    }
}

// ---------------------------------------------------------------------------
// final: combine everything into the scalar loss. (512 dice partials)
// ---------------------------------------------------------------------------
__global__ __launch_bounds__(256) void final_kernel(float* __restrict__ out) {
    __shared__ float s[3][256];
    {
        int i0 = threadIdx.x, i1 = threadIdx.x + 256;
        s[0][threadIdx.x] = g_dicePart[i0*3 + 0] + g_dicePart[i1*3 + 0];
        s[1][threadIdx.x] = g_dicePart[i0*3 + 1] + g_dicePart[i1*3 + 1];
        s[2][threadIdx.x] = g_dicePart[i0*3 + 2] + g_dicePart[i1*3 + 2];
    }
    __syncthreads();
    for (int off = 128; off > 0; off >>= 1) {
        if (threadIdx.x < off) {
            s[0][threadIdx.x] += s[0][threadIdx.x + off];
            s[1][threadIdx.x] += s[1][threadIdx.x + off];
            s[2][threadIdx.x] += s[2][threadIdx.x + off];
        }
        __syncthreads();
    }
    __shared__ float S[NIMG], SY[NIMG], SX[NIMG];
    if (threadIdx.x < NIMG) {
        float t0 = 0.f, t1 = 0.f, t2 = 0.f;
        for (int bd = 0; bd < NBANDS; bd++) {
            int o = (threadIdx.x*NBANDS + bd)*3;
            t0 += g_epPart[o + 0];
            t1 += g_epPart[o + 1];
            t2 += g_epPart[o + 2];
        }
        S[threadIdx.x] = t0; SY[threadIdx.x] = t1; SX[threadIdx.x] = t2;
    }
    __syncthreads();
    if (threadIdx.x == 0) {
        float inter = s[0][0], sumT = s[1][0], sumP = s[2][0];
        float dice = 1.f - (2.f*inter + 1.f) / (sumT + sumP + 1.f);
        float distsum = 0.f, cntsum = 0.f;
        for (int b = 0; b < NB; b++) {
            float np = S[b], nt = S[NB + b];
            float tp = np + 1e-8f, tt = nt + 1e-8f;
            float ycp = SY[b] / tp,      xcp = SX[b] / tp;
            float yct = SY[NB+b] / tt,   xct = SX[NB+b] / tt;
            float dy = ycp - yct, dx = xcp - xct;
            distsum += sqrtf(dy*dy + dx*dx);
            cntsum  += fabsf(np - nt) / (np + nt + 1e-8f);
        }
        float diag = sqrtf((float)(H*H) + (float)(W*W));
        float distance_loss = (distsum / (float)NB) / (diag * 1.0f + 1e-8f);
        float count_penalty = cntsum / (float)NB;
        out[0] = 0.85f * dice + 0.15f * (distance_loss + count_penalty);
    }
}

// ---------------------------------------------------------------------------
extern "C" void kernel_launch(void* const* d_in, const int* in_sizes, int n_in,
                              void* d_out, int out_size) {
    const float* net = (const float*)d_in[0];
    const int*   yt  = (const int*)d_in[1];
    float* out = (float*)d_out;
    (void)in_sizes; (void)n_in; (void)out_size;

    prep_kernel<<<PREP_BLOCKS, 256>>>(net, yt);

    dim3 grid(NBANDS, NIMG);
    sweep_init_kernel<<<grid, 128>>>();             // q init; img stays in A
    for (int i = 0; i < NUM_ITER-1; i++)            // iterations 0..38
        sweep_step_kernel<<<grid, 128>>>(i & 1);
    final_step_kernel<<<grid, 128>>>((NUM_ITER-1) & 1);  // iter 39 + endpoint
    final_kernel<<<1, 256>>>(out);
}

// round 17
// speedup vs baseline: 1.0699x; 1.0699x over previous
#include <cuda_runtime.h>
#include <math.h>

#define H 512
#define W 512
#define HW (512*512)
#define NB 8          // batch
#define NIMG 16       // 8 pred + 8 true
#define NUM_ITER 40
#define BH 16
#define NBANDS (H/BH)   // 32
#define BIGF 3.0e38f
#define PREP_BLOCKS 512

// ---- scratch (device globals; no allocation) ----
// g_skel stores q = 1 - skel  (multiplicative form: q *= (1 - delta))
__device__ float g_imgA[(size_t)NIMG*HW];
__device__ float g_imgB[(size_t)NIMG*HW];
__device__ float g_skel[(size_t)NIMG*HW];
__device__ float g_dicePart[PREP_BLOCKS*3];   // [block][inter,sumT,sumP]
__device__ float g_epPart[NIMG*NBANDS*3];     // [img][band][s,sy,sx]

__device__ __forceinline__ float f3min(float a,float b,float c){return fminf(fminf(a,b),c);}
__device__ __forceinline__ float f3max(float a,float b,float c){return fmaxf(fmaxf(a,b),c);}

// ---------------------------------------------------------------------------
// prep: prob = sigmoid(x1-x0); true->float; dice partials. (vectorized)
// ---------------------------------------------------------------------------
__global__ __launch_bounds__(256) void prep_kernel(const float* __restrict__ net,
                                                   const int* __restrict__ yt) {
    const int b   = blockIdx.x >> 6;          // image 0..7
    const int seg = blockIdx.x & 63;          // segment 0..63
    const int tid = threadIdx.x;
    const float4* x0p = (const float4*)(net + (size_t)b*2*HW);
    const float4* x1p = (const float4*)(net + (size_t)b*2*HW + HW);
    const int4*   ytp = (const int4*)(yt + (size_t)b*HW);
    float4* probp = (float4*)(g_imgA + (size_t)b*HW);
    float4* truep = (float4*)(g_imgA + (size_t)(NB + b)*HW);

    float inter = 0.f, st = 0.f, sp = 0.f;
    #pragma unroll
    for (int j = 0; j < 4; j++) {
        int i = seg*1024 + j*256 + tid;       // float4 index within image
        float4 x0 = x0p[i];
        float4 x1 = x1p[i];
        int4 ti = ytp[i];
        float4 pr;
        pr.x = 1.f / (1.f + __expf(x0.x - x1.x));
        pr.y = 1.f / (1.f + __expf(x0.y - x1.y));
        pr.z = 1.f / (1.f + __expf(x0.z - x1.z));
        pr.w = 1.f / (1.f + __expf(x0.w - x1.w));
        float4 tf = make_float4((float)ti.x, (float)ti.y, (float)ti.z, (float)ti.w);
        probp[i] = pr;
        truep[i] = tf;
        inter += tf.x*pr.x + tf.y*pr.y + tf.z*pr.z + tf.w*pr.w;
        st += tf.x + tf.y + tf.z + tf.w;
        sp += pr.x + pr.y + pr.z + pr.w;
    }
    __shared__ float s[3][256];
    s[0][tid] = inter; s[1][tid] = st; s[2][tid] = sp;
    __syncthreads();
    for (int off = 128; off > 0; off >>= 1) {
        if (tid < off) {
            s[0][tid] += s[0][tid + off];
            s[1][tid] += s[1][tid + off];
            s[2][tid] += s[2][tid + off];
        }
        __syncthreads();
    }
    if (tid == 0) {
        g_dicePart[blockIdx.x*3 + 0] = s[0][0];
        g_dicePart[blockIdx.x*3 + 1] = s[1][0];
        g_dicePart[blockIdx.x*3 + 2] = s[2][0];
    }
}

// ---------------------------------------------------------------------------
// INIT sweep: q = 1 - relu(img - dilate3x3(erode(img))). FULLY UNROLLED.
// ---------------------------------------------------------------------------
__global__ __launch_bounds__(128, 4) void sweep_init_kernel() {
    const int img = blockIdx.y;
    const int R0row = blockIdx.x * BH;
    const int lane = threadIdx.x & 31;
    const int colBase = ((threadIdx.x >> 5) << 7) + (lane << 2);
    const bool isL = (lane == 0), isR = (lane == 31);
    const bool edgeL = (colBase == 0), edgeR = (colBase == W-4);
    const float* __restrict__ in = g_imgA + (size_t)img*HW;
    float* __restrict__ skel = g_skel + (size_t)img*HW;

    const float4 PINF = make_float4(BIGF,BIGF,BIGF,BIGF);
    float4 i0=PINF, i1=PINF, L0=PINF, L1=PINF, Rv0=PINF, Rv1=PINF;
    float4 hp=PINF; float hpL1=BIGF, hpR0=BIGF;
    float4 e1a=make_float4(-BIGF,-BIGF,-BIGF,-BIGF), e1b=e1a;
    float e1aL=-BIGF, e1bL=-BIGF, e1aR=-BIGF, e1bR=-BIGF;

    const int rStart = R0row-2, rEnd = R0row+BH+1;   // BH+4 = 20 rows
    float4 nCur=PINF, nL=PINF, nR=PINF;
    if (rStart >= 0 && rStart < H) {
        const float* p = in + rStart*W + colBase;
        nCur = *(const float4*)p;
        if (isL && !edgeL) nL = *(const float4*)(p - 4);
        if (isR && !edgeR) nR = *(const float4*)(p + 4);
    }

    #pragma unroll
    for (int t = 0; t < BH+4; t++) {
        const int r = rStart + t;
        float4 cur = nCur, Lc = nL, Rc = nR;
        nCur = PINF; nL = PINF; nR = PINF;
        {
            int rn = r + 1;
            if (rn <= rEnd && (unsigned)rn < (unsigned)H) {
                const float* p = in + rn*W + colBase;
                nCur = *(const float4*)p;
                if (isL && !edgeL) nL = *(const float4*)(p - 4);
                if (isR && !edgeR) nR = *(const float4*)(p + 4);
            }
        }
        float xm1 = __shfl_up_sync(0xffffffffu, cur.w, 1); if (isL) xm1 = Lc.w;
        float xp1 = __shfl_down_sync(0xffffffffu, cur.x, 1); if (isR) xp1 = Rc.x;
        float4 hc;
        hc.x = f3min(xm1, cur.x, cur.y);
        hc.y = f3min(cur.x, cur.y, cur.z);
        hc.z = f3min(cur.y, cur.z, cur.w);
        hc.w = f3min(cur.z, cur.w, xp1);
        float hcL1 = f3min(Lc.z, Lc.w, cur.x);
        float hcR0 = f3min(cur.w, Rc.x, Rc.y);

        float4 e1n;
        e1n.x = fminf(f3min(i0.x,i1.x,cur.x), hp.x);
        e1n.y = fminf(f3min(i0.y,i1.y,cur.y), hp.y);
        e1n.z = fminf(f3min(i0.z,i1.z,cur.z), hp.z);
        e1n.w = fminf(f3min(i0.w,i1.w,cur.w), hp.w);
        float e1nL = fminf(f3min(L0.w,L1.w,Lc.w), hpL1);
        float e1nR = fminf(f3min(Rv0.x,Rv1.x,Rc.x), hpR0);
        {
            int k = r-1;
            if (k < 0 || k >= H) {
                e1n = make_float4(-BIGF,-BIGF,-BIGF,-BIGF);
                e1nL = e1nR = -BIGF;
            }
        }
        if (edgeL) e1nL = -BIGF;
        if (edgeR) e1nR = -BIGF;

        if (t >= 4) {   // r >= R0row+2
            float4 mv;
            mv.x = f3max(e1a.x, e1b.x, e1n.x);
            mv.y = f3max(e1a.y, e1b.y, e1n.y);
            mv.z = f3max(e1a.z, e1b.z, e1n.z);
            mv.w = f3max(e1a.w, e1b.w, e1n.w);
            float mvL = f3max(e1aL, e1bL, e1nL);
            float mvR = f3max(e1aR, e1bR, e1nR);
            float mm1 = __shfl_up_sync(0xffffffffu, mv.w, 1); if (isL) mm1 = mvL;
            float mp1 = __shfl_down_sync(0xffffffffu, mv.x, 1); if (isR) mp1 = mvR;
            float4 open;
            open.x = f3max(mm1, mv.x, mv.y);
            open.y = f3max(mv.x, mv.y, mv.z);
            open.z = f3max(mv.y, mv.z, mv.w);
            open.w = f3max(mv.z, mv.w, mp1);
            int k2 = r-2;
            float4 s;
            s.x = 1.f - fmaxf(i0.x - open.x, 0.f);
            s.y = 1.f - fmaxf(i0.y - open.y, 0.f);
            s.z = 1.f - fmaxf(i0.z - open.z, 0.f);
            s.w = 1.f - fmaxf(i0.w - open.w, 0.f);
            *(float4*)(skel + k2*W + colBase) = s;
        }
        i0=i1; i1=cur; L0=L1; L1=Lc; Rv0=Rv1; Rv1=Rc;
        hp=hc; hpL1=hcL1; hpR0=hcR0;
        e1a=e1b; e1b=e1n; e1aL=e1bL; e1bL=e1nL; e1aR=e1bR; e1bR=e1nR;
    }
}

// ---------------------------------------------------------------------------
// STEP body (iterations 0..38), FULLY UNROLLED. (R14/R15 winner, no prefetch)
// ---------------------------------------------------------------------------
template<bool BOUNDARY>
__device__ __forceinline__ void step_body(
    const float* __restrict__ in, float* __restrict__ outImg,
    float* __restrict__ skel, int R0row, int colBase,
    bool isL, bool isR, bool edgeL, bool edgeR)
{
    const float4 PINF = make_float4(BIGF,BIGF,BIGF,BIGF);
    const float4 NINF = make_float4(-BIGF,-BIGF,-BIGF,-BIGF);

    float4 i0=PINF, i1=PINF, L0=PINF, L1=PINF, Rv0=PINF, Rv1=PINF;
    float4 hp=PINF; float hpL0=BIGF, hpL1=BIGF, hpR0=BIGF, hpR1=BIGF;
    float4 e1a=PINF, e1b=PINF; float e1aL=BIGF, e1bL=BIGF, e1aR=BIGF, e1bR=BIGF;
    float4 h1p=PINF; float h1pL=BIGF, h1pR=BIGF;
    float4 e2a=NINF, e2b=NINF; float e2aL=-BIGF, e2bL=-BIGF, e2aR=-BIGF, e2bR=-BIGF;

    const int rStart = R0row-3, rEnd = R0row+BH+2;   // BH+6 = 22 rows
    float4 nCur=PINF, nL=PINF, nR=PINF, nSk=make_float4(0,0,0,0);
    if (!BOUNDARY || (rStart >= 0 && rStart < H)) {
        const float* p = in + rStart*W + colBase;
        nCur = *(const float4*)p;
        if (isL && !edgeL) nL = *(const float4*)(p - 4);
        if (isR && !edgeR) nR = *(const float4*)(p + 4);
    }

    #pragma unroll
    for (int t = 0; t < BH+6; t++) {
        const int r = rStart + t;
        float4 cur = nCur, Lc = nL, Rc = nR, skv = nSk;
        {
            int rn = r + 1;
            if (BOUNDARY) {
                nCur = PINF; nL = PINF; nR = PINF;
                if (rn <= rEnd && (unsigned)rn < (unsigned)H) {
                    const float* p = in + rn*W + colBase;
                    nCur = *(const float4*)p;
                    if (isL && !edgeL) nL = *(const float4*)(p - 4);
                    if (isR && !edgeR) nR = *(const float4*)(p + 4);
                }
                if (rn >= R0row+3 && rn <= rEnd)
                    nSk = *(const float4*)(skel + (rn-3)*W + colBase);
            } else {
                const float* p = in + rn*W + colBase;
                nCur = *(const float4*)p;
                nL = PINF; nR = PINF;
                if (isL && !edgeL) nL = *(const float4*)(p - 4);
                if (isR && !edgeR) nR = *(const float4*)(p + 4);
                nSk = *(const float4*)(skel + (rn-3)*W + colBase);
            }
        }
        float xm1 = __shfl_up_sync(0xffffffffu, cur.w, 1); if (isL) xm1 = Lc.w;
        float xp1 = __shfl_down_sync(0xffffffffu, cur.x, 1); if (isR) xp1 = Rc.x;
        float4 hc;
        hc.x = f3min(xm1, cur.x, cur.y);
        hc.y = f3min(cur.x, cur.y, cur.z);
        hc.z = f3min(cur.y, cur.z, cur.w);
        hc.w = f3min(cur.z, cur.w, xp1);
        float hcL0 = f3min(Lc.y, Lc.z, Lc.w);
        float hcL1 = f3min(Lc.z, Lc.w, cur.x);
        float hcR0 = f3min(cur.w, Rc.x, Rc.y);
        float hcR1 = f3min(Rc.x, Rc.y, Rc.z);

        float4 e1n;
        e1n.x = fminf(f3min(i0.x,i1.x,cur.x), hp.x);
        e1n.y = fminf(f3min(i0.y,i1.y,cur.y), hp.y);
        e1n.z = fminf(f3min(i0.z,i1.z,cur.z), hp.z);
        e1n.w = fminf(f3min(i0.w,i1.w,cur.w), hp.w);
        float e1nL0 = fminf(f3min(L0.z,L1.z,Lc.z), hpL0);
        float e1nL1 = fminf(f3min(L0.w,L1.w,Lc.w), hpL1);
        float e1nR0 = fminf(f3min(Rv0.x,Rv1.x,Rc.x), hpR0);
        float e1nR1 = fminf(f3min(Rv0.y,Rv1.y,Rc.y), hpR1);
        if (BOUNDARY) {
            int k = r-1;
            if (k < 0 || k >= H) { e1n = PINF; e1nL0=e1nL1=e1nR0=e1nR1=BIGF; }
        }
        float em1 = __shfl_up_sync(0xffffffffu, e1n.w, 1); if (isL) em1 = e1nL1;
        float ep1 = __shfl_down_sync(0xffffffffu, e1n.x, 1); if (isR) ep1 = e1nR0;
        float4 h1c;
        h1c.x = f3min(em1, e1n.x, e1n.y);
        h1c.y = f3min(e1n.x, e1n.y, e1n.z);
        h1c.z = f3min(e1n.y, e1n.z, e1n.w);
        h1c.w = f3min(e1n.z, e1n.w, ep1);
        float h1cL = f3min(e1nL0, e1nL1, e1n.x);
        float h1cR = f3min(e1n.w, e1nR0, e1nR1);

        float4 e2n;
        e2n.x = fminf(f3min(e1a.x,e1b.x,e1n.x), h1p.x);
        e2n.y = fminf(f3min(e1a.y,e1b.y,e1n.y), h1p.y);
        e2n.z = fminf(f3min(e1a.z,e1b.z,e1n.z), h1p.z);
        e2n.w = fminf(f3min(e1a.w,e1b.w,e1n.w), h1p.w);
        float e2nL = fminf(f3min(e1aL,e1bL,e1nL1), h1pL);
        float e2nR = fminf(f3min(e1aR,e1bR,e1nR0), h1pR);
        if (BOUNDARY) {
            int j = r-2;
            if (j < 0 || j >= H) { e2n = NINF; e2nL = e2nR = -BIGF; }
        }
        if (edgeL) e2nL = -BIGF;
        if (edgeR) e2nR = -BIGF;

        if (t >= 6) {
            float4 mv;
            mv.x = f3max(e2a.x, e2b.x, e2n.x);
            mv.y = f3max(e2a.y, e2b.y, e2n.y);
            mv.z = f3max(e2a.z, e2b.z, e2n.z);
            mv.w = f3max(e2a.w, e2b.w, e2n.w);
            float mvL = f3max(e2aL, e2bL, e2nL);
            float mvR = f3max(e2aR, e2bR, e2nR);
            float mm1 = __shfl_up_sync(0xffffffffu, mv.w, 1); if (isL) mm1 = mvL;
            float mp1 = __shfl_down_sync(0xffffffffu, mv.x, 1); if (isR) mp1 = mvR;
            float4 open;
            open.x = f3max(mm1, mv.x, mv.y);
            open.y = f3max(mv.x, mv.y, mv.z);
            open.z = f3max(mv.y, mv.z, mv.w);
            open.w = f3max(mv.z, mv.w, mp1);
            int k2 = r-3;
            float4 ec = e1a;
            float4 q = skv;
            float d0 = fmaxf(ec.x - open.x, 0.f); q.x -= q.x*d0;
            float d1 = fmaxf(ec.y - open.y, 0.f); q.y -= q.y*d1;
            float d2 = fmaxf(ec.z - open.z, 0.f); q.z -= q.z*d2;
            float d3 = fmaxf(ec.w - open.w, 0.f); q.w -= q.w*d3;
            *(float4*)(skel + k2*W + colBase) = q;
            *(float4*)(outImg + k2*W + colBase) = ec;
        }
        i0=i1; i1=cur; L0=L1; L1=Lc; Rv0=Rv1; Rv1=Rc;
        hp=hc; hpL0=hcL0; hpL1=hcL1; hpR0=hcR0; hpR1=hcR1;
        e1a=e1b; e1b=e1n; e1aL=e1bL; e1bL=e1nL1; e1aR=e1bR; e1bR=e1nR0;
        h1p=h1c; h1pL=h1cL; h1pR=h1cR;
        e2a=e2b; e2b=e2n; e2aL=e2bL; e2bL=e2nL; e2aR=e2bR; e2bR=e2nR;
    }
}

__global__ __launch_bounds__(128, 4) void sweep_step_kernel(int bufsel) {
    const int img = blockIdx.y;
    const int band = blockIdx.x;
    const int R0row = band * BH;
    const int lane = threadIdx.x & 31;
    const int colBase = ((threadIdx.x >> 5) << 7) + (lane << 2);
    const bool isL = (lane == 0), isR = (lane == 31);
    const bool edgeL = (colBase == 0), edgeR = (colBase == W-4);
    const float* __restrict__ in     = (bufsel ? g_imgB : g_imgA) + (size_t)img*HW;
    float*       __restrict__ outImg = (bufsel ? g_imgA : g_imgB) + (size_t)img*HW;
    float*       __restrict__ skel   = g_skel + (size_t)img*HW;

    if (band == 0 || band == NBANDS-1)
        step_body<true >(in, outImg, skel, R0row, colBase, isL, isR, edgeL, edgeR);
    else
        step_body<false>(in, outImg, skel, R0row, colBase, isL, isR, edgeL, edgeR);
}

// ---------------------------------------------------------------------------
// FINAL fused kernel: last morphology iteration + endpoint conv + partials.
// ---------------------------------------------------------------------------
#define SROWS 18
#define SPITCH 516
template<bool BOUNDARY>
__device__ __forceinline__ void final_body(
    const float* __restrict__ in, const float* __restrict__ skel,
    int R0row, int colBase,
    bool isL, bool isR, bool edgeL, bool edgeR,
    float (*sk_s)[SPITCH])
{
    const float4 PINF = make_float4(BIGF,BIGF,BIGF,BIGF);
    const float4 NINF = make_float4(-BIGF,-BIGF,-BIGF,-BIGF);

    float4 i0=PINF, i1=PINF, L0=PINF, L1=PINF, Rv0=PINF, Rv1=PINF;
    float4 hp=PINF; float hpL0=BIGF, hpL1=BIGF, hpR0=BIGF, hpR1=BIGF;
    float4 e1a=PINF, e1b=PINF; float e1aL=BIGF, e1bL=BIGF, e1aR=BIGF, e1bR=BIGF;
    float4 h1p=PINF; float h1pL=BIGF, h1pR=BIGF;
    float4 e2a=NINF, e2b=NINF; float e2aL=-BIGF, e2bL=-BIGF, e2aR=-BIGF, e2bR=-BIGF;

    const int rStart = R0row-4;               // 24 rows: t = 0..BH+7
    float4 nCur=PINF, nL=PINF, nR=PINF, nSk=make_float4(0,0,0,0);
    if (!BOUNDARY || ((unsigned)rStart < (unsigned)H)) {
        const float* p = in + rStart*W + colBase;
        nCur = *(const float4*)p;
        if (isL && !edgeL) nL = *(const float4*)(p - 4);
        if (isR && !edgeR) nR = *(const float4*)(p + 4);
    }

    #pragma unroll
    for (int t = 0; t < BH+8; t++) {
        const int r = rStart + t;
        float4 cur = nCur, Lc = nL, Rc = nR, skv = nSk;
        {
            int rn = r + 1;   // prefetch img row rn and q row rn-3
            if (BOUNDARY) {
                nCur = PINF; nL = PINF; nR = PINF;
                if ((unsigned)rn < (unsigned)H && t+1 <= BH+7) {
                    const float* p = in + rn*W + colBase;
                    nCur = *(const float4*)p;
                    if (isL && !edgeL) nL = *(const float4*)(p - 4);
                    if (isR && !edgeR) nR = *(const float4*)(p + 4);
                }
                nSk = make_float4(0,0,0,0);
                if (t+1 >= 6 && t+1 <= BH+7 && (unsigned)(rn-3) < (unsigned)H)
                    nSk = *(const float4*)(skel + (rn-3)*W + colBase);
            } else {
                if (t+1 <= BH+7) {
                    const float* p = in + rn*W + colBase;
                    nCur = *(const float4*)p;
                    nL = PINF; nR = PINF;
                    if (isL && !edgeL) nL = *(const float4*)(p - 4);
                    if (isR && !edgeR) nR = *(const float4*)(p + 4);
                }
                if (t+1 >= 6 && t+1 <= BH+7)
                    nSk = *(const float4*)(skel + (rn-3)*W + colBase);
            }
        }
        float xm1 = __shfl_up_sync(0xffffffffu, cur.w, 1); if (isL) xm1 = Lc.w;
        float xp1 = __shfl_down_sync(0xffffffffu, cur.x, 1); if (isR) xp1 = Rc.x;
        float4 hc;
        hc.x = f3min(xm1, cur.x, cur.y);
        hc.y = f3min(cur.x, cur.y, cur.z);
        hc.z = f3min(cur.y, cur.z, cur.w);
        hc.w = f3min(cur.z, cur.w, xp1);
        float hcL0 = f3min(Lc.y, Lc.z, Lc.w);
        float hcL1 = f3min(Lc.z, Lc.w, cur.x);
        float hcR0 = f3min(cur.w, Rc.x, Rc.y);
        float hcR1 = f3min(Rc.x, Rc.y, Rc.z);

        float4 e1n;
        e1n.x = fminf(f3min(i0.x,i1.x,cur.x), hp.x);
        e1n.y = fminf(f3min(i0.y,i1.y,cur.y), hp.y);
        e1n.z = fminf(f3min(i0.z,i1.z,cur.z), hp.z);
        e1n.w = fminf(f3min(i0.w,i1.w,cur.w), hp.w);
        float e1nL0 = fminf(f3min(L0.z,L1.z,Lc.z), hpL0);
        float e1nL1 = fminf(f3min(L0.w,L1.w,Lc.w), hpL1);
        float e1nR0 = fminf(f3min(Rv0.x,Rv1.x,Rc.x), hpR0);
        float e1nR1 = fminf(f3min(Rv0.y,Rv1.y,Rc.y), hpR1);
        if (BOUNDARY) {
            int k = r-1;
            if (k < 0 || k >= H) { e1n = PINF; e1nL0=e1nL1=e1nR0=e1nR1=BIGF; }
        }
        float em1 = __shfl_up_sync(0xffffffffu, e1n.w, 1); if (isL) em1 = e1nL1;
        float ep1 = __shfl_down_sync(0xffffffffu, e1n.x, 1); if (isR) ep1 = e1nR0;
        float4 h1c;
        h1c.x = f3min(em1, e1n.x, e1n.y);
        h1c.y = f3min(e1n.x, e1n.y, e1n.z);
        h1c.z = f3min(e1n.y, e1n.z, e1n.w);
        h1c.w = f3min(e1n.z, e1n.w, ep1);
        float h1cL = f3min(e1nL0, e1nL1, e1n.x);
        float h1cR = f3min(e1n.w, e1nR0, e1nR1);

        float4 e2n;
        e2n.x = fminf(f3min(e1a.x,e1b.x,e1n.x), h1p.x);
        e2n.y = fminf(f3min(e1a.y,e1b.y,e1n.y), h1p.y);
        e2n.z = fminf(f3min(e1a.z,e1b.z,e1n.z), h1p.z);
        e2n.w = fminf(f3min(e1a.w,e1b.w,e1n.w), h1p.w);
        float e2nL = fminf(f3min(e1aL,e1bL,e1nL1), h1pL);
        float e2nR = fminf(f3min(e1aR,e1bR,e1nR0), h1pR);
        if (BOUNDARY) {
            int j = r-2;
            if (j < 0 || j >= H) { e2n = NINF; e2nL = e2nR = -BIGF; }
        }
        if (edgeL) e2nL = -BIGF;
        if (edgeR) e2nR = -BIGF;

        if (t >= 6) {   // out row k2 = r-3 in [R0row-1, R0row+BH]; smem row t-6
            const int k2 = r-3;
            const int srow = t-6;
            float4 sv = make_float4(0,0,0,0);   // zero-pad for invalid rows
            if (!BOUNDARY || ((unsigned)k2 < (unsigned)H)) {
                float4 mv;
                mv.x = f3max(e2a.x, e2b.x, e2n.x);
                mv.y = f3max(e2a.y, e2b.y, e2n.y);
                mv.z = f3max(e2a.z, e2b.z, e2n.z);
                mv.w = f3max(e2a.w, e2b.w, e2n.w);
                float mvL = f3max(e2aL, e2bL, e2nL);
                float mvR = f3max(e2aR, e2bR, e2nR);
                float mm1 = __shfl_up_sync(0xffffffffu, mv.w, 1); if (isL) mm1 = mvL;
                float mp1 = __shfl_down_sync(0xffffffffu, mv.x, 1); if (isR) mp1 = mvR;
                float4 open;
                open.x = f3max(mm1, mv.x, mv.y);
                open.y = f3max(mv.x, mv.y, mv.z);
                open.z = f3max(mv.y, mv.z, mv.w);
                open.w = f3max(mv.z, mv.w, mp1);
                float4 ec = e1a;
                float4 q = skv;
                float d0 = fmaxf(ec.x - open.x, 0.f); q.x -= q.x*d0;
                float d1 = fmaxf(ec.y - open.y, 0.f); q.y -= q.y*d1;
                float d2 = fmaxf(ec.z - open.z, 0.f); q.z -= q.z*d2;
                float d3 = fmaxf(ec.w - open.w, 0.f); q.w -= q.w*d3;
                sv = make_float4(1.f-q.x, 1.f-q.y, 1.f-q.z, 1.f-q.w);
            } else {
                // keep warp-uniform shfl execution even when row invalid
                float4 mv;
                mv.x = f3max(e2a.x, e2b.x, e2n.x);
                mv.w = f3max(e2a.w, e2b.w, e2n.w);
                (void)__shfl_up_sync(0xffffffffu, mv.w, 1);
                (void)__shfl_down_sync(0xffffffffu, mv.x, 1);
            }
            *(float4*)&sk_s[srow][colBase] = sv;
        }
        i0=i1; i1=cur; L0=L1; L1=Lc; Rv0=Rv1; Rv1=Rc;
        hp=hc; hpL0=hcL0; hpL1=hcL1; hpR0=hcR0; hpR1=hcR1;
        e1a=e1b; e1b=e1n; e1aL=e1bL; e1bL=e1nL1; e1aR=e1bR; e1bR=e1nR0;
        h1p=h1c; h1pL=h1cL; h1pR=h1cR;
        e2a=e2b; e2b=e2n; e2aL=e2bL; e2bL=e2nL; e2aR=e2bR; e2bR=e2nR;
    }
}

__global__ __launch_bounds__(128, 4) void final_step_kernel(int bufsel) {
    const int img = blockIdx.y;
    const int band = blockIdx.x;
    const int R0row = band * BH;
    const int lane = threadIdx.x & 31;
    const int colBase = ((threadIdx.x >> 5) << 7) + (lane << 2);
    const bool isL = (lane == 0), isR = (lane == 31);
    const bool edgeL = (colBase == 0), edgeR = (colBase == W-4);
    const float* __restrict__ in   = (bufsel ? g_imgB : g_imgA) + (size_t)img*HW;
    const float* __restrict__ skel = g_skel + (size_t)img*HW;

    __shared__ float sk_s[SROWS][SPITCH];

    if (band == 0 || band == NBANDS-1)
        final_body<true >(in, skel, R0row, colBase, isL, isR, edgeL, edgeR, sk_s);
    else
        final_body<false>(in, skel, R0row, colBase, isL, isR, edgeL, edgeR, sk_s);

    __syncthreads();

    float r0c[6], r1c[6], r2c[6];
    #pragma unroll
    for (int j = 0; j < 6; j++) { r0c[j] = 0.f; r1c[j] = 0.f; }
    {
        #pragma unroll
        for (int s = 0; s < 2; s++) {
            float* dst = s ? r1c : r0c;
            const float* row = sk_s[s];
            dst[0] = edgeL ? 0.f : row[colBase-1];
            float4 v = *(const float4*)&row[colBase];
            dst[1]=v.x; dst[2]=v.y; dst[3]=v.z; dst[4]=v.w;
            dst[5] = edgeR ? 0.f : row[colBase+4];
        }
    }
    float s0 = 0.f, sy = 0.f, sx = 0.f;
    #pragma unroll
    for (int kk = 0; kk < BH; kk++) {
        const float* row = sk_s[kk+2];
        r2c[0] = edgeL ? 0.f : row[colBase-1];
        float4 v = *(const float4*)&row[colBase];
        r2c[1]=v.x; r2c[2]=v.y; r2c[3]=v.z; r2c[4]=v.w;
        r2c[5] = edgeR ? 0.f : row[colBase+4];

        float vs0 = r0c[0]+r1c[0]+r2c[0];
        float vs1 = r0c[1]+r1c[1]+r2c[1];
        float vs2 = r0c[2]+r1c[2]+r2c[2];
        float vs3 = r0c[3]+r1c[3]+r2c[3];
        float vs4 = r0c[4]+r1c[4]+r2c[4];
        float vs5 = r0c[5]+r1c[5]+r2c[5];
        float c0 = r1c[1], c1 = r1c[2], c2 = r1c[3], c3 = r1c[4];
        float ns0 = vs0+vs1+vs2 + 9.f*c0;
        float ns1 = vs1+vs2+vs3 + 9.f*c1;
        float ns2 = vs2+vs3+vs4 + 9.f*c2;
        float ns3 = vs3+vs4+vs5 + 9.f*c3;
        float d0 = ns0-11.f, d1 = ns1-11.f, d2 = ns2-11.f, d3 = ns3-11.f;
        float e0 = __expf(-d0*d0)*c0;
        float e1 = __expf(-d1*d1)*c1;
        float e2 = __expf(-d2*d2)*c2;
        float e3 = __expf(-d3*d3)*c3;
        float es = e0+e1+e2+e3;
        s0 += es;
        sy += es * (float)(R0row + kk);
        sx += e0*(float)colBase + e1*(float)(colBase+1)
            + e2*(float)(colBase+2) + e3*(float)(colBase+3);
        #pragma unroll
        for (int j = 0; j < 6; j++) { r0c[j] = r1c[j]; r1c[j] = r2c[j]; }
    }

    __syncthreads();
    __shared__ float s[3][128];
    s[0][threadIdx.x] = s0; s[1][threadIdx.x] = sy; s[2][threadIdx.x] = sx;
    __syncthreads();
    for (int off = 64; off > 0; off >>= 1) {
        if (threadIdx.x < off) {
            s[0][threadIdx.x] += s[0][threadIdx.x + off];
            s[1][threadIdx.x] += s[1][threadIdx.x + off];
            s[2][threadIdx.x] += s[2][threadIdx.x + off];
        }
        __syncthreads();
    }
    if (threadIdx.x == 0) {
        int o = (img*NBANDS + band)*3;
        g_epPart[o + 0] = s[0][0];
        g_epPart[o + 1] = s[1][0];
        g_epPart[o + 2] = s[2][0];
    }
}

// ---------------------------------------------------------------------------
// final: combine everything into the scalar loss. (512 dice partials)
// ---------------------------------------------------------------------------
__global__ __launch_bounds__(256) void final_kernel(float* __restrict__ out) {
    __shared__ float s[3][256];
    {
        int i0 = threadIdx.x, i1 = threadIdx.x + 256;
        s[0][threadIdx.x] = g_dicePart[i0*3 + 0] + g_dicePart[i1*3 + 0];
        s[1][threadIdx.x] = g_dicePart[i0*3 + 1] + g_dicePart[i1*3 + 1];
        s[2][threadIdx.x] = g_dicePart[i0*3 + 2] + g_dicePart[i1*3 + 2];
    }
    __syncthreads();
    for (int off = 128; off > 0; off >>= 1) {
        if (threadIdx.x < off) {
            s[0][threadIdx.x] += s[0][threadIdx.x + off];
            s[1][threadIdx.x] += s[1][threadIdx.x + off];
            s[2][threadIdx.x] += s[2][threadIdx.x + off];
        }
        __syncthreads();
    }
    __shared__ float S[NIMG], SY[NIMG], SX[NIMG];
    if (threadIdx.x < NIMG) {
        float t0 = 0.f, t1 = 0.f, t2 = 0.f;
        for (int bd = 0; bd < NBANDS; bd++) {
            int o = (threadIdx.x*NBANDS + bd)*3;
            t0 += g_epPart[o + 0];
            t1 += g_epPart[o + 1];
            t2 += g_epPart[o + 2];
        }
        S[threadIdx.x] = t0; SY[threadIdx.x] = t1; SX[threadIdx.x] = t2;
    }
    __syncthreads();
    if (threadIdx.x == 0) {
        float inter = s[0][0], sumT = s[1][0], sumP = s[2][0];
        float dice = 1.f - (2.f*inter + 1.f) / (sumT + sumP + 1.f);
        float distsum = 0.f, cntsum = 0.f;
        for (int b = 0; b < NB; b++) {
            float np = S[b], nt = S[NB + b];
            float tp = np + 1e-8f, tt = nt + 1e-8f;
            float ycp = SY[b] / tp,      xcp = SX[b] / tp;
            float yct = SY[NB+b] / tt,   xct = SX[NB+b] / tt;
            float dy = ycp - yct, dx = xcp - xct;
            distsum += sqrtf(dy*dy + dx*dx);
            cntsum  += fabsf(np - nt) / (np + nt + 1e-8f);
        }
        float diag = sqrtf((float)(H*H) + (float)(W*W));
        float distance_loss = (distsum / (float)NB) / (diag * 1.0f + 1e-8f);
        float count_penalty = cntsum / (float)NB;
        out[0] = 0.85f * dice + 0.15f * (distance_loss + count_penalty);
    }
}

// ---------------------------------------------------------------------------
extern "C" void kernel_launch(void* const* d_in, const int* in_sizes, int n_in,
                              void* d_out, int out_size) {
    const float* net = (const float*)d_in[0];
    const int*   yt  = (const int*)d_in[1];
    float* out = (float*)d_out;
    (void)in_sizes; (void)n_in; (void)out_size;

    prep_kernel<<<PREP_BLOCKS, 256>>>(net, yt);

    dim3 grid(NBANDS, NIMG);
    sweep_init_kernel<<<grid, 128>>>();             // q init; img stays in A
    for (int i = 0; i < NUM_ITER-1; i++)            // iterations 0..38
        sweep_step_kernel<<<grid, 128>>>(i & 1);
    final_step_kernel<<<grid, 128>>>((NUM_ITER-1) & 1);  // iter 39 + endpoint
    final_kernel<<<1, 256>>>(out);
}